// round 1
// baseline (speedup 1.0000x reference)
#include <cuda_runtime.h>
#include <math.h>

#define B_   8
#define N_   2048
#define D_   64
#define H_   8
#define M_   (B_*N_)        // 16384 rows
#define QKVN (3*H_*D_)      // 1536
#define HD   (H_*D_)        // 512

// Scratch (allocation-free rule: __device__ globals)
__device__ float g_qkv[(size_t)M_ * QKVN];  // [16384, 1536]
__device__ float g_z  [(size_t)M_ * HD];    // [16384, 512]

// ---------------------------------------------------------------------------
// Generic tiled SGEMM: C[M,N] = A[M,K] @ B[K,N] (+ bias). 256 threads,
// 64xBN tile, 4x4 micro-tile per thread.
// ---------------------------------------------------------------------------
template<int BM, int BN, int BK, bool BIAS>
__global__ __launch_bounds__(256)
void sgemm_kernel(const float* __restrict__ A,
                  const float* __restrict__ Bm,
                  const float* __restrict__ bias,
                  float* __restrict__ C,
                  int M, int N, int K)
{
    __shared__ float As[BK][BM + 4];   // transposed A tile, padded
    __shared__ float Bs[BK][BN];

    const int tid = threadIdx.x;
    const int tx  = tid % (BN / 4);
    const int ty  = tid / (BN / 4);
    const int m0  = blockIdx.y * BM;
    const int n0  = blockIdx.x * BN;

    float acc[4][4] = {};

    for (int k0 = 0; k0 < K; k0 += BK) {
        // Load A tile (BM x BK), store transposed As[k][m]
        #pragma unroll
        for (int idx = tid; idx < BM * BK / 4; idx += 256) {
            int row = idx / (BK / 4);
            int c4  = idx % (BK / 4);
            float4 a = *(const float4*)(A + (size_t)(m0 + row) * K + k0 + c4 * 4);
            As[c4 * 4 + 0][row] = a.x;
            As[c4 * 4 + 1][row] = a.y;
            As[c4 * 4 + 2][row] = a.z;
            As[c4 * 4 + 3][row] = a.w;
        }
        // Load B tile (BK x BN)
        #pragma unroll
        for (int idx = tid; idx < BK * BN / 4; idx += 256) {
            int row = idx / (BN / 4);
            int c4  = idx % (BN / 4);
            *(float4*)&Bs[row][c4 * 4] =
                *(const float4*)(Bm + (size_t)(k0 + row) * N + n0 + c4 * 4);
        }
        __syncthreads();

        #pragma unroll
        for (int k = 0; k < BK; k++) {
            float4 a = *(const float4*)&As[k][ty * 4];
            float4 b = *(const float4*)&Bs[k][tx * 4];
            float av[4] = {a.x, a.y, a.z, a.w};
            float bv[4] = {b.x, b.y, b.z, b.w};
            #pragma unroll
            for (int i = 0; i < 4; i++)
                #pragma unroll
                for (int j = 0; j < 4; j++)
                    acc[i][j] = fmaf(av[i], bv[j], acc[i][j]);
        }
        __syncthreads();
    }

    #pragma unroll
    for (int i = 0; i < 4; i++) {
        float4 o;
        o.x = acc[i][0]; o.y = acc[i][1]; o.z = acc[i][2]; o.w = acc[i][3];
        if (BIAS) {
            o.x += bias[n0 + tx * 4 + 0];
            o.y += bias[n0 + tx * 4 + 1];
            o.z += bias[n0 + tx * 4 + 2];
            o.w += bias[n0 + tx * 4 + 3];
        }
        *(float4*)(C + (size_t)(m0 + ty * 4 + i) * N + n0 + tx * 4) = o;
    }
}

// ---------------------------------------------------------------------------
// Flash attention (fp32): one block per (b, h, 128-q-row tile).
// One thread owns one q row; q and o live in registers; K/V staged via smem
// (all threads broadcast-read the same K/V row -> conflict-free LDS).
// Online softmax in register chunks of 16 scores.
// ---------------------------------------------------------------------------
#define BQ  128
#define BKV 64

__global__ __launch_bounds__(BQ)
void attn_kernel(const float* __restrict__ qkv, float* __restrict__ z)
{
    __shared__ float ks[BKV][D_];
    __shared__ float vs[BKV][D_];

    const int bh = blockIdx.y;
    const int b  = bh >> 3;
    const int h  = bh & 7;
    const int t  = threadIdx.x;
    const int qrow = blockIdx.x * BQ + t;

    // Load my q row into registers, fold in 1/sqrt(d)
    const float* qp = qkv + ((size_t)(b * N_ + qrow)) * QKVN + h * D_;
    float q[D_];
    #pragma unroll
    for (int d4 = 0; d4 < D_ / 4; d4++) {
        float4 v = *(const float4*)(qp + d4 * 4);
        q[d4 * 4 + 0] = v.x * 0.125f;
        q[d4 * 4 + 1] = v.y * 0.125f;
        q[d4 * 4 + 2] = v.z * 0.125f;
        q[d4 * 4 + 3] = v.w * 0.125f;
    }

    float o[D_];
    #pragma unroll
    for (int d = 0; d < D_; d++) o[d] = 0.f;
    float m = -1e30f, l = 0.f;

    const float* kb = qkv + ((size_t)b * N_) * QKVN + HD + h * D_;
    const float* vb = kb + HD;

    for (int j0 = 0; j0 < N_; j0 += BKV) {
        // Cooperative coalesced K/V tile load
        #pragma unroll
        for (int idx = t; idx < BKV * (D_ / 4); idx += BQ) {
            int r = idx >> 4;
            int c = (idx & 15) * 4;
            size_t go = (size_t)(j0 + r) * QKVN + c;
            *(float4*)&ks[r][c] = *(const float4*)(kb + go);
            *(float4*)&vs[r][c] = *(const float4*)(vb + go);
        }
        __syncthreads();

        #pragma unroll 1
        for (int jc = 0; jc < BKV; jc += 16) {
            float s[16];
            #pragma unroll
            for (int jj = 0; jj < 16; jj++) {
                float acc = 0.f;
                #pragma unroll
                for (int d = 0; d < D_; d++)
                    acc = fmaf(q[d], ks[jc + jj][d], acc);
                s[jj] = acc;
            }
            float mc = s[0];
            #pragma unroll
            for (int jj = 1; jj < 16; jj++) mc = fmaxf(mc, s[jj]);
            float mn   = fmaxf(m, mc);
            float corr = __expf(m - mn);
            l *= corr;
            #pragma unroll
            for (int d = 0; d < D_; d++) o[d] *= corr;
            #pragma unroll
            for (int jj = 0; jj < 16; jj++) {
                float p = __expf(s[jj] - mn);
                l += p;
                #pragma unroll
                for (int d = 0; d < D_; d++)
                    o[d] = fmaf(p, vs[jc + jj][d], o[d]);
            }
            m = mn;
        }
        __syncthreads();
    }

    const float inv = 1.f / l;
    float* zp = z + ((size_t)(b * N_ + qrow)) * HD + h * D_;
    #pragma unroll
    for (int d4 = 0; d4 < D_ / 4; d4++) {
        float4 v;
        v.x = o[d4 * 4 + 0] * inv;
        v.y = o[d4 * 4 + 1] * inv;
        v.z = o[d4 * 4 + 2] * inv;
        v.w = o[d4 * 4 + 3] * inv;
        *(float4*)(zp + d4 * 4) = v;
    }
}

// ---------------------------------------------------------------------------
extern "C" void kernel_launch(void* const* d_in, const int* in_sizes, int n_in,
                              void* d_out, int out_size)
{
    const float* x    = (const float*)d_in[0];  // [8,2048,64]
    const float* Wqkv = (const float*)d_in[1];  // [64,1536]
    const float* Wout = (const float*)d_in[2];  // [512,64]
    const float* bout = (const float*)d_in[3];  // [64]
    float* out = (float*)d_out;                 // [8,2048,64]

    float* qkvp = nullptr;
    float* zp   = nullptr;
    cudaGetSymbolAddress((void**)&qkvp, g_qkv);
    cudaGetSymbolAddress((void**)&zp,   g_z);

    // 1) QKV projection: [16384,64] @ [64,1536]
    {
        dim3 grid(QKVN / 64, M_ / 64);
        sgemm_kernel<64, 64, 64, false><<<grid, 256>>>(x, Wqkv, nullptr, qkvp,
                                                       M_, QKVN, D_);
    }
    // 2) Attention
    {
        dim3 grid(N_ / BQ, B_ * H_);
        attn_kernel<<<grid, BQ>>>(qkvp, zp);
    }
    // 3) Output projection: [16384,512] @ [512,64] + b
    {
        dim3 grid(1, M_ / 64);
        sgemm_kernel<64, 64, 32, true><<<grid, 256>>>(zp, Wout, bout, out,
                                                      M_, D_, HD);
    }
}

// round 2
// speedup vs baseline: 4.2895x; 4.2895x over previous
#include <cuda_runtime.h>
#include <math.h>
#include <stdint.h>

#define B_   8
#define N_   2048
#define D_   64
#define H_   8
#define M_   (B_*N_)        // 16384 rows
#define QKVN (3*H_*D_)      // 1536
#define HD   (H_*D_)        // 512

// Scratch (allocation-free rule: __device__ globals)
__device__ float g_qkv[(size_t)M_ * QKVN];  // [16384, 1536]
__device__ float g_z  [(size_t)M_ * HD];    // [16384, 512]

// ---------------------------------------------------------------------------
// helpers
// ---------------------------------------------------------------------------
__device__ __forceinline__ uint32_t f2tf32(float f) {
    uint32_t r;
    asm("cvt.rna.tf32.f32 %0, %1;" : "=r"(r) : "f"(f));
    return r;
}

__device__ __forceinline__ void mma_tf32(float d[4], const uint32_t a[4],
                                         uint32_t b0, uint32_t b1) {
    asm volatile(
        "mma.sync.aligned.m16n8k8.row.col.f32.tf32.tf32.f32 "
        "{%0,%1,%2,%3}, {%4,%5,%6,%7}, {%8,%9}, {%0,%1,%2,%3};\n"
        : "+f"(d[0]), "+f"(d[1]), "+f"(d[2]), "+f"(d[3])
        : "r"(a[0]), "r"(a[1]), "r"(a[2]), "r"(a[3]), "r"(b0), "r"(b1));
}

// swizzle: pair-level XOR; s_p(row) = ((row&3)<<2) | ((row&4)>>1)
__device__ __forceinline__ int sw_f4(int row, int c4) {          // float4 slot
    return c4 ^ (((row & 3) << 1) | ((row & 4) >> 2));
}
__device__ __forceinline__ int sw_col(int row, int col) {        // element
    int sp = ((row & 3) << 2) | ((row & 4) >> 1);
    return ((((col >> 1) ^ sp) << 1) | (col & 1));
}

// ---------------------------------------------------------------------------
// Generic tiled SGEMM (unchanged from R1): C[M,N] = A[M,K] @ B[K,N] (+bias)
// ---------------------------------------------------------------------------
template<int BM, int BN, int BK, bool BIAS>
__global__ __launch_bounds__(256)
void sgemm_kernel(const float* __restrict__ A,
                  const float* __restrict__ Bm,
                  const float* __restrict__ bias,
                  float* __restrict__ C,
                  int M, int N, int K)
{
    __shared__ float As[BK][BM + 4];
    __shared__ float Bs[BK][BN];

    const int tid = threadIdx.x;
    const int tx  = tid % (BN / 4);
    const int ty  = tid / (BN / 4);
    const int m0  = blockIdx.y * BM;
    const int n0  = blockIdx.x * BN;

    float acc[4][4] = {};

    for (int k0 = 0; k0 < K; k0 += BK) {
        #pragma unroll
        for (int idx = tid; idx < BM * BK / 4; idx += 256) {
            int row = idx / (BK / 4);
            int c4  = idx % (BK / 4);
            float4 a = *(const float4*)(A + (size_t)(m0 + row) * K + k0 + c4 * 4);
            As[c4 * 4 + 0][row] = a.x;
            As[c4 * 4 + 1][row] = a.y;
            As[c4 * 4 + 2][row] = a.z;
            As[c4 * 4 + 3][row] = a.w;
        }
        #pragma unroll
        for (int idx = tid; idx < BK * BN / 4; idx += 256) {
            int row = idx / (BN / 4);
            int c4  = idx % (BN / 4);
            *(float4*)&Bs[row][c4 * 4] =
                *(const float4*)(Bm + (size_t)(k0 + row) * N + n0 + c4 * 4);
        }
        __syncthreads();

        #pragma unroll
        for (int k = 0; k < BK; k++) {
            float4 a = *(const float4*)&As[k][ty * 4];
            float4 b = *(const float4*)&Bs[k][tx * 4];
            float av[4] = {a.x, a.y, a.z, a.w};
            float bv[4] = {b.x, b.y, b.z, b.w};
            #pragma unroll
            for (int i = 0; i < 4; i++)
                #pragma unroll
                for (int j = 0; j < 4; j++)
                    acc[i][j] = fmaf(av[i], bv[j], acc[i][j]);
        }
        __syncthreads();
    }

    #pragma unroll
    for (int i = 0; i < 4; i++) {
        float4 o;
        o.x = acc[i][0]; o.y = acc[i][1]; o.z = acc[i][2]; o.w = acc[i][3];
        if (BIAS) {
            o.x += bias[n0 + tx * 4 + 0];
            o.y += bias[n0 + tx * 4 + 1];
            o.z += bias[n0 + tx * 4 + 2];
            o.w += bias[n0 + tx * 4 + 3];
        }
        *(float4*)(C + (size_t)(m0 + ty * 4 + i) * N + n0 + tx * 4) = o;
    }
}

// ---------------------------------------------------------------------------
// Flash attention with tf32 mma.sync.
// Block: 128 q rows, 4 warps; each warp = 2 m-tiles (32 q rows).
// KV tile = 64, staged in smem with XOR swizzle (conflict-free b-frag LDS).
// ---------------------------------------------------------------------------
__global__ __launch_bounds__(128)
void attn_mma_kernel(const float* __restrict__ qkv, float* __restrict__ z)
{
    __shared__ uint32_t ks[64 * 64];
    __shared__ uint32_t vs[64 * 64];

    const int tid  = threadIdx.x;
    const int warp = tid >> 5;
    const int lane = tid & 31;
    const int r    = lane >> 2;     // 0..7
    const int qq   = lane & 3;      // 0..3
    const int bh   = blockIdx.y;
    const int b    = bh >> 3;
    const int h    = bh & 7;
    const int q0   = blockIdx.x * 128 + warp * 32;

    const float* qkv_b = qkv + (size_t)b * N_ * QKVN;

    // ---- Q fragments (A layout), scale folded in --------------------------
    uint32_t qa[2][8][4];
    #pragma unroll
    for (int mt = 0; mt < 2; mt++) {
        const float* p0 = qkv_b + (size_t)(q0 + mt * 16 + r) * QKVN + h * D_;
        const float* p1 = p0 + 8 * (size_t)QKVN;
        #pragma unroll
        for (int kt = 0; kt < 8; kt++) {
            qa[mt][kt][0] = f2tf32(p0[kt * 8 + qq]     * 0.125f);
            qa[mt][kt][1] = f2tf32(p1[kt * 8 + qq]     * 0.125f);
            qa[mt][kt][2] = f2tf32(p0[kt * 8 + qq + 4] * 0.125f);
            qa[mt][kt][3] = f2tf32(p1[kt * 8 + qq + 4] * 0.125f);
        }
    }

    float o[2][8][4];
    #pragma unroll
    for (int mt = 0; mt < 2; mt++)
        #pragma unroll
        for (int nt = 0; nt < 8; nt++)
            #pragma unroll
            for (int i = 0; i < 4; i++) o[mt][nt][i] = 0.f;

    float mrow[2][2] = {{-1e30f, -1e30f}, {-1e30f, -1e30f}};
    float lrow[2][2] = {{0.f, 0.f}, {0.f, 0.f}};

    const float* kbase = qkv_b + HD + h * D_;
    const float* vbase = kbase + HD;

    // per-lane swizzle constants
    const int sp_r = ((r & 3) << 2) | ((r & 4) >> 1);  // s_p for rows ≡ r (mod 8)

    for (int j0 = 0; j0 < N_; j0 += 64) {
        // ---- load K,V tile (coalesced, tf32-rounded, swizzled) ------------
        #pragma unroll
        for (int it = 0; it < 8; it++) {
            int idx = tid + it * 128;
            int rr  = idx >> 4;
            int c4  = idx & 15;
            int f4  = sw_f4(rr, c4);
            size_t go = (size_t)(j0 + rr) * QKVN + c4 * 4;
            float4 kv4 = *(const float4*)(kbase + go);
            uint4 kc;
            kc.x = f2tf32(kv4.x); kc.y = f2tf32(kv4.y);
            kc.z = f2tf32(kv4.z); kc.w = f2tf32(kv4.w);
            *(uint4*)&ks[rr * 64 + f4 * 4] = kc;
            float4 vv4 = *(const float4*)(vbase + go);
            uint4 vc;
            vc.x = f2tf32(vv4.x); vc.y = f2tf32(vv4.y);
            vc.z = f2tf32(vv4.z); vc.w = f2tf32(vv4.w);
            *(uint4*)&vs[rr * 64 + f4 * 4] = vc;
        }
        __syncthreads();

        // ---- S = Q @ K^T ---------------------------------------------------
        float sc[2][8][4];
        #pragma unroll
        for (int mt = 0; mt < 2; mt++)
            #pragma unroll
            for (int nt = 0; nt < 8; nt++)
                #pragma unroll
                for (int i = 0; i < 4; i++) sc[mt][nt][i] = 0.f;

        #pragma unroll
        for (int kt = 0; kt < 8; kt++) {
            // b-frag col indices (element-swizzled), shared across nt
            int pair0 = 4 * kt + (qq >> 1);
            int col0  = (((pair0)     ^ sp_r) << 1) | (qq & 1);
            int col1  = (((pair0 + 2) ^ sp_r) << 1) | (qq & 1);
            #pragma unroll
            for (int nt = 0; nt < 8; nt++) {
                int row = nt * 8 + r;
                uint32_t b0 = ks[row * 64 + col0];
                uint32_t b1 = ks[row * 64 + col1];
                mma_tf32(sc[0][nt], qa[0][kt], b0, b1);
                mma_tf32(sc[1][nt], qa[1][kt], b0, b1);
            }
        }

        // ---- online softmax on C-layout ------------------------------------
        #pragma unroll
        for (int mt = 0; mt < 2; mt++) {
            float mx0 = -1e30f, mx1 = -1e30f;
            #pragma unroll
            for (int nt = 0; nt < 8; nt++) {
                mx0 = fmaxf(mx0, fmaxf(sc[mt][nt][0], sc[mt][nt][1]));
                mx1 = fmaxf(mx1, fmaxf(sc[mt][nt][2], sc[mt][nt][3]));
            }
            mx0 = fmaxf(mx0, __shfl_xor_sync(0xffffffffu, mx0, 1));
            mx0 = fmaxf(mx0, __shfl_xor_sync(0xffffffffu, mx0, 2));
            mx1 = fmaxf(mx1, __shfl_xor_sync(0xffffffffu, mx1, 1));
            mx1 = fmaxf(mx1, __shfl_xor_sync(0xffffffffu, mx1, 2));
            float mn0 = fmaxf(mrow[mt][0], mx0);
            float mn1 = fmaxf(mrow[mt][1], mx1);
            float c0 = __expf(mrow[mt][0] - mn0);
            float c1 = __expf(mrow[mt][1] - mn1);
            mrow[mt][0] = mn0; mrow[mt][1] = mn1;
            lrow[mt][0] *= c0; lrow[mt][1] *= c1;
            float l0 = 0.f, l1 = 0.f;
            #pragma unroll
            for (int nt = 0; nt < 8; nt++) {
                o[mt][nt][0] *= c0; o[mt][nt][1] *= c0;
                o[mt][nt][2] *= c1; o[mt][nt][3] *= c1;
                float p0 = __expf(sc[mt][nt][0] - mn0);
                float p1 = __expf(sc[mt][nt][1] - mn0);
                float p2 = __expf(sc[mt][nt][2] - mn1);
                float p3 = __expf(sc[mt][nt][3] - mn1);
                l0 += p0 + p1; l1 += p2 + p3;
                sc[mt][nt][0] = p0; sc[mt][nt][1] = p1;
                sc[mt][nt][2] = p2; sc[mt][nt][3] = p3;
            }
            lrow[mt][0] += l0; lrow[mt][1] += l1;
        }

        // ---- O += P @ V -----------------------------------------------------
        const int src0 = (lane & 28) | (qq >> 1);
        const int src1 = src0 + 2;
        #pragma unroll
        for (int kt = 0; kt < 8; kt++) {
            // P: C-layout (cols 2q,2q+1) -> A-layout (cols q, q+4) via shfl
            uint32_t pa[2][4];
            #pragma unroll
            for (int mt = 0; mt < 2; mt++) {
                float x0 = __shfl_sync(0xffffffffu, sc[mt][kt][0], src0);
                float x1 = __shfl_sync(0xffffffffu, sc[mt][kt][1], src0);
                float y0 = __shfl_sync(0xffffffffu, sc[mt][kt][2], src0);
                float y1 = __shfl_sync(0xffffffffu, sc[mt][kt][3], src0);
                float u0 = __shfl_sync(0xffffffffu, sc[mt][kt][0], src1);
                float u1 = __shfl_sync(0xffffffffu, sc[mt][kt][1], src1);
                float w0 = __shfl_sync(0xffffffffu, sc[mt][kt][2], src1);
                float w1 = __shfl_sync(0xffffffffu, sc[mt][kt][3], src1);
                pa[mt][0] = f2tf32((qq & 1) ? x1 : x0);
                pa[mt][1] = f2tf32((qq & 1) ? y1 : y0);
                pa[mt][2] = f2tf32((qq & 1) ? u1 : u0);
                pa[mt][3] = f2tf32((qq & 1) ? w1 : w0);
            }
            // V b-frags: row = kt*8 + qq (+4), col = nt*8 + r
            int rowv0 = kt * 8 + qq;
            int rowv1 = rowv0 + 4;
            #pragma unroll
            for (int nt = 0; nt < 8; nt++) {
                int colv = nt * 8 + r;
                uint32_t b0 = vs[rowv0 * 64 + sw_col(rowv0, colv)];
                uint32_t b1 = vs[rowv1 * 64 + sw_col(rowv1, colv)];
                mma_tf32(o[0][nt], pa[0], b0, b1);
                mma_tf32(o[1][nt], pa[1], b0, b1);
            }
        }
        __syncthreads();
    }

    // ---- finalize: 1/l, write O -------------------------------------------
    #pragma unroll
    for (int mt = 0; mt < 2; mt++) {
        float l0 = lrow[mt][0];
        l0 += __shfl_xor_sync(0xffffffffu, l0, 1);
        l0 += __shfl_xor_sync(0xffffffffu, l0, 2);
        float l1 = lrow[mt][1];
        l1 += __shfl_xor_sync(0xffffffffu, l1, 1);
        l1 += __shfl_xor_sync(0xffffffffu, l1, 2);
        float inv0 = 1.f / l0, inv1 = 1.f / l1;
        int row0 = q0 + mt * 16 + r;
        float* zp0 = z + (size_t)(b * N_ + row0) * HD + h * D_;
        float* zp1 = zp0 + 8 * (size_t)HD;
        #pragma unroll
        for (int nt = 0; nt < 8; nt++) {
            int col = nt * 8 + 2 * qq;
            float2 v0 = {o[mt][nt][0] * inv0, o[mt][nt][1] * inv0};
            float2 v1 = {o[mt][nt][2] * inv1, o[mt][nt][3] * inv1};
            *(float2*)(zp0 + col) = v0;
            *(float2*)(zp1 + col) = v1;
        }
    }
}

// ---------------------------------------------------------------------------
extern "C" void kernel_launch(void* const* d_in, const int* in_sizes, int n_in,
                              void* d_out, int out_size)
{
    const float* x    = (const float*)d_in[0];  // [8,2048,64]
    const float* Wqkv = (const float*)d_in[1];  // [64,1536]
    const float* Wout = (const float*)d_in[2];  // [512,64]
    const float* bout = (const float*)d_in[3];  // [64]
    float* out = (float*)d_out;                 // [8,2048,64]

    float* qkvp = nullptr;
    float* zp   = nullptr;
    cudaGetSymbolAddress((void**)&qkvp, g_qkv);
    cudaGetSymbolAddress((void**)&zp,   g_z);

    // 1) QKV projection: [16384,64] @ [64,1536]
    {
        dim3 grid(QKVN / 64, M_ / 64);
        sgemm_kernel<64, 64, 64, false><<<grid, 256>>>(x, Wqkv, nullptr, qkvp,
                                                       M_, QKVN, D_);
    }
    // 2) Attention (tf32 tensor cores)
    {
        dim3 grid(N_ / 128, B_ * H_);
        attn_mma_kernel<<<grid, 128>>>(qkvp, zp);
    }
    // 3) Output projection: [16384,512] @ [512,64] + b
    {
        dim3 grid(1, M_ / 64);
        sgemm_kernel<64, 64, 32, true><<<grid, 256>>>(zp, Wout, bout, out,
                                                      M_, D_, HD);
    }
}

// round 3
// speedup vs baseline: 6.4717x; 1.5087x over previous
#include <cuda_runtime.h>
#include <cuda_fp16.h>
#include <math.h>
#include <stdint.h>

#define B_   8
#define N_   2048
#define D_   64
#define H_   8
#define M_   (B_*N_)        // 16384 rows
#define QKVN (3*H_*D_)      // 1536
#define HD   (H_*D_)        // 512
#define QSCALE (0.125f * 1.44269504088896f)   // 1/sqrt(d) * log2(e)

// Scratch (allocation-free rule: __device__ globals)
__device__ float  g_qkv[(size_t)M_ * QKVN];        // Q,K regions used
__device__ __half g_vt [(size_t)B_*H_*D_*N_];      // V transposed [bh][d][tok]
__device__ float  g_z  [(size_t)M_ * HD];

// ---------------------------------------------------------------------------
// helpers
// ---------------------------------------------------------------------------
__device__ __forceinline__ uint32_t f2tf32(float f) {
    uint32_t r;
    asm("cvt.rna.tf32.f32 %0, %1;" : "=r"(r) : "f"(f));
    return r;
}
__device__ __forceinline__ float ex2f(float x) {
    float y;
    asm("ex2.approx.f32 %0, %1;" : "=f"(y) : "f"(x));
    return y;
}
__device__ __forceinline__ uint32_t packh2(float lo, float hi) {
    uint32_t u;
    asm("cvt.rn.f16x2.f32 %0, %1, %2;" : "=r"(u) : "f"(hi), "f"(lo));
    return u;
}
__device__ __forceinline__ void mma_tf32(float d[4], const uint32_t a[4],
                                         uint32_t b0, uint32_t b1) {
    asm volatile(
        "mma.sync.aligned.m16n8k8.row.col.f32.tf32.tf32.f32 "
        "{%0,%1,%2,%3}, {%4,%5,%6,%7}, {%8,%9}, {%0,%1,%2,%3};\n"
        : "+f"(d[0]), "+f"(d[1]), "+f"(d[2]), "+f"(d[3])
        : "r"(a[0]), "r"(a[1]), "r"(a[2]), "r"(a[3]), "r"(b0), "r"(b1));
}
__device__ __forceinline__ void mma_f16(float d[4], const uint32_t a[4],
                                        uint32_t b0, uint32_t b1) {
    asm volatile(
        "mma.sync.aligned.m16n8k16.row.col.f32.f16.f16.f32 "
        "{%0,%1,%2,%3}, {%4,%5,%6,%7}, {%8,%9}, {%0,%1,%2,%3};\n"
        : "+f"(d[0]), "+f"(d[1]), "+f"(d[2]), "+f"(d[3])
        : "r"(a[0]), "r"(a[1]), "r"(a[2]), "r"(a[3]), "r"(b0), "r"(b1));
}
__device__ __forceinline__ void cp16(uint32_t dst_smem, const void* src) {
    asm volatile("cp.async.cg.shared.global [%0], [%1], 16;\n"
                 :: "r"(dst_smem), "l"(src));
}
// K swizzle: float4-slot XOR (same as R2)
__device__ __forceinline__ int sw_f4(int row, int c4) {
    return c4 ^ (((row & 3) << 1) | ((row & 4) >> 2));
}

// ---------------------------------------------------------------------------
// QKV GEMM: [16384,64] @ [64,1536], epilogue writes
//   Q (n<512):  tf32-rounded, *QSCALE        -> g_qkv
//   K (n<1024): tf32-rounded                 -> g_qkv
//   V (else):   fp16, transposed [bh][d][tok]-> g_vt
// ---------------------------------------------------------------------------
__global__ __launch_bounds__(256)
void qkv_gemm_kernel(const float* __restrict__ A,
                     const float* __restrict__ Bm,
                     float* __restrict__ Cq,
                     __half* __restrict__ vt)
{
    const int BM = 64, BN = 64, BK = 64;
    __shared__ float As[64][64 + 4];
    __shared__ float Bs[64][64];

    const int tid = threadIdx.x;
    const int tx  = tid % 16;
    const int ty  = tid / 16;
    const int m0  = blockIdx.y * BM;
    const int n0  = blockIdx.x * BN;
    const int K = 64, Nn = QKVN;

    float acc[4][4] = {};

    #pragma unroll
    for (int idx = tid; idx < BM * BK / 4; idx += 256) {
        int row = idx / 16;
        int c4  = idx % 16;
        float4 a = *(const float4*)(A + (size_t)(m0 + row) * K + c4 * 4);
        As[c4 * 4 + 0][row] = a.x;
        As[c4 * 4 + 1][row] = a.y;
        As[c4 * 4 + 2][row] = a.z;
        As[c4 * 4 + 3][row] = a.w;
    }
    #pragma unroll
    for (int idx = tid; idx < BK * BN / 4; idx += 256) {
        int row = idx / 16;
        int c4  = idx % 16;
        *(float4*)&Bs[row][c4 * 4] =
            *(const float4*)(Bm + (size_t)row * Nn + n0 + c4 * 4);
    }
    __syncthreads();

    #pragma unroll
    for (int k = 0; k < BK; k++) {
        float4 a = *(const float4*)&As[k][ty * 4];
        float4 b = *(const float4*)&Bs[k][tx * 4];
        float av[4] = {a.x, a.y, a.z, a.w};
        float bv[4] = {b.x, b.y, b.z, b.w};
        #pragma unroll
        for (int i = 0; i < 4; i++)
            #pragma unroll
            for (int j = 0; j < 4; j++)
                acc[i][j] = fmaf(av[i], bv[j], acc[i][j]);
    }

    const int ncol = n0 + tx * 4;
    if (ncol < 1024) {
        const float s = (ncol < 512) ? QSCALE : 1.0f;
        #pragma unroll
        for (int i = 0; i < 4; i++) {
            float4 o;
            o.x = __uint_as_float(f2tf32(acc[i][0] * s));
            o.y = __uint_as_float(f2tf32(acc[i][1] * s));
            o.z = __uint_as_float(f2tf32(acc[i][2] * s));
            o.w = __uint_as_float(f2tf32(acc[i][3] * s));
            *(float4*)(Cq + (size_t)(m0 + ty * 4 + i) * QKVN + ncol) = o;
        }
    } else {
        const int tok0 = m0 + ty * 4;
        const int b    = tok0 >> 11;
        const int ntok = tok0 & 2047;
        #pragma unroll
        for (int j = 0; j < 4; j++) {
            int dg = ncol + j - 1024;          // 0..511
            int h  = dg >> 6;
            int d  = dg & 63;
            __half2 lo = __floats2half2_rn(acc[0][j], acc[1][j]);
            __half2 hi = __floats2half2_rn(acc[2][j], acc[3][j]);
            uint2 u;
            u.x = *(uint32_t*)&lo;
            u.y = *(uint32_t*)&hi;
            *(uint2*)(vt + ((size_t)((b * 8 + h) * 64 + d)) * N_ + ntok) = u;
        }
    }
}

// ---------------------------------------------------------------------------
// Flash attention: tf32 QK^T + fp16 P@V (C-frag == A-frag trick, no shuffles),
// exp2-domain softmax, double-buffered cp.async K/V tiles.
// ---------------------------------------------------------------------------
#define VSTRIDE 88    // halves per d-row in smem (conflict-free, 16B-aligned)

__global__ __launch_bounds__(128)
void attn_kernel(const float* __restrict__ qkv,
                 const __half* __restrict__ vt,
                 float* __restrict__ z)
{
    extern __shared__ char smem_raw[];
    uint32_t* ks = (uint32_t*)smem_raw;                       // 2 * 4096 u32
    __half*   vs = (__half*)(smem_raw + 2 * 4096 * 4);        // 2 * 64*88 h

    const int tid  = threadIdx.x;
    const int warp = tid >> 5;
    const int lane = tid & 31;
    const int r    = lane >> 2;
    const int qq   = lane & 3;
    const int bh   = blockIdx.y;
    const int b    = bh >> 3;
    const int h    = bh & 7;
    const int q0   = blockIdx.x * 128 + warp * 32;

    // Q fragments: already tf32-rounded and scaled in gmem -> plain LDG
    uint32_t qa[2][8][4];
    #pragma unroll
    for (int mt = 0; mt < 2; mt++) {
        const uint32_t* p0 = (const uint32_t*)
            (qkv + (size_t)(b * N_ + q0 + mt * 16 + r) * QKVN + h * D_);
        const uint32_t* p1 = p0 + 8 * (size_t)QKVN;
        #pragma unroll
        for (int kt = 0; kt < 8; kt++) {
            qa[mt][kt][0] = p0[kt * 8 + qq];
            qa[mt][kt][1] = p1[kt * 8 + qq];
            qa[mt][kt][2] = p0[kt * 8 + qq + 4];
            qa[mt][kt][3] = p1[kt * 8 + qq + 4];
        }
    }

    float o[2][8][4];
    #pragma unroll
    for (int mt = 0; mt < 2; mt++)
        #pragma unroll
        for (int nt = 0; nt < 8; nt++)
            #pragma unroll
            for (int i = 0; i < 4; i++) o[mt][nt][i] = 0.f;

    float mrow[2][2] = {{-1e30f, -1e30f}, {-1e30f, -1e30f}};
    float lrow[2][2] = {{0.f, 0.f}, {0.f, 0.f}};

    const float*  kb = qkv + (size_t)b * N_ * QKVN + HD + h * D_;
    const __half* vb = vt + (size_t)bh * D_ * N_;

    const uint32_t ks_base = (uint32_t)__cvta_generic_to_shared(ks);
    const uint32_t vs_base = (uint32_t)__cvta_generic_to_shared(vs);

    const int sp_r = ((r & 3) << 2) | ((r & 4) >> 1);

#define CP_TILE(stage, j0) do {                                               \
    _Pragma("unroll")                                                         \
    for (int it = 0; it < 8; it++) {                                          \
        int idx = tid + it * 128;                                             \
        int rr = idx >> 4, c4 = idx & 15;                                     \
        cp16(ks_base + (uint32_t)(((stage) * 4096 + rr * 64 +                 \
                                   sw_f4(rr, c4) * 4) * 4),                   \
             kb + (size_t)((j0) + rr) * QKVN + c4 * 4);                       \
    }                                                                         \
    _Pragma("unroll")                                                         \
    for (int it = 0; it < 4; it++) {                                          \
        int idx = tid + it * 128;                                             \
        int dd = idx >> 3, c8 = idx & 7;                                      \
        cp16(vs_base + (uint32_t)(((stage) * 64 * VSTRIDE + dd * VSTRIDE +    \
                                   c8 * 8) * 2),                              \
             vb + (size_t)dd * N_ + (j0) + c8 * 8);                           \
    }                                                                         \
    asm volatile("cp.async.commit_group;\n" ::);                              \
} while (0)

    CP_TILE(0, 0);

    for (int t = 0; t < N_ / 64; t++) {
        const int s = t & 1;
        if (t < N_ / 64 - 1) {
            CP_TILE(s ^ 1, (t + 1) * 64);
            asm volatile("cp.async.wait_group 1;\n" ::);
        } else {
            asm volatile("cp.async.wait_group 0;\n" ::);
        }
        __syncthreads();

        const uint32_t* kss = ks + s * 4096;
        const __half*   vss = vs + s * 64 * VSTRIDE;

        // ---- S = Q @ K^T (tf32) ----
        float sc[2][8][4];
        #pragma unroll
        for (int mt = 0; mt < 2; mt++)
            #pragma unroll
            for (int nt = 0; nt < 8; nt++)
                #pragma unroll
                for (int i = 0; i < 4; i++) sc[mt][nt][i] = 0.f;

        #pragma unroll
        for (int kt = 0; kt < 8; kt++) {
            int pair0 = 4 * kt + (qq >> 1);
            int col0  = ((pair0 ^ sp_r) << 1) | (qq & 1);
            int col1  = (((pair0 + 2) ^ sp_r) << 1) | (qq & 1);
            #pragma unroll
            for (int nt = 0; nt < 8; nt++) {
                int row = nt * 8 + r;
                uint32_t b0 = kss[row * 64 + col0];
                uint32_t b1 = kss[row * 64 + col1];
                mma_tf32(sc[0][nt], qa[0][kt], b0, b1);
                mma_tf32(sc[1][nt], qa[1][kt], b0, b1);
            }
        }

        // ---- online softmax (log2 domain) ----
        #pragma unroll
        for (int mt = 0; mt < 2; mt++) {
            float mx0 = -1e30f, mx1 = -1e30f;
            #pragma unroll
            for (int nt = 0; nt < 8; nt++) {
                mx0 = fmaxf(mx0, fmaxf(sc[mt][nt][0], sc[mt][nt][1]));
                mx1 = fmaxf(mx1, fmaxf(sc[mt][nt][2], sc[mt][nt][3]));
            }
            mx0 = fmaxf(mx0, __shfl_xor_sync(0xffffffffu, mx0, 1));
            mx0 = fmaxf(mx0, __shfl_xor_sync(0xffffffffu, mx0, 2));
            mx1 = fmaxf(mx1, __shfl_xor_sync(0xffffffffu, mx1, 1));
            mx1 = fmaxf(mx1, __shfl_xor_sync(0xffffffffu, mx1, 2));
            float mn0 = fmaxf(mrow[mt][0], mx0);
            float mn1 = fmaxf(mrow[mt][1], mx1);
            float c0 = ex2f(mrow[mt][0] - mn0);
            float c1 = ex2f(mrow[mt][1] - mn1);
            mrow[mt][0] = mn0; mrow[mt][1] = mn1;
            lrow[mt][0] *= c0; lrow[mt][1] *= c1;
            float l0 = 0.f, l1 = 0.f;
            #pragma unroll
            for (int nt = 0; nt < 8; nt++) {
                o[mt][nt][0] *= c0; o[mt][nt][1] *= c0;
                o[mt][nt][2] *= c1; o[mt][nt][3] *= c1;
                float p0 = ex2f(sc[mt][nt][0] - mn0);
                float p1 = ex2f(sc[mt][nt][1] - mn0);
                float p2 = ex2f(sc[mt][nt][2] - mn1);
                float p3 = ex2f(sc[mt][nt][3] - mn1);
                l0 += p0 + p1; l1 += p2 + p3;
                sc[mt][nt][0] = p0; sc[mt][nt][1] = p1;
                sc[mt][nt][2] = p2; sc[mt][nt][3] = p3;
            }
            lrow[mt][0] += l0; lrow[mt][1] += l1;
        }

        // ---- O += P @ V (fp16, C-frag == A-frag, zero shuffles) ----
        #pragma unroll
        for (int kt = 0; kt < 4; kt++) {        // k16 chunks over kv
            uint32_t pa[2][4];
            #pragma unroll
            for (int mt = 0; mt < 2; mt++) {
                pa[mt][0] = packh2(sc[mt][2*kt  ][0], sc[mt][2*kt  ][1]);
                pa[mt][1] = packh2(sc[mt][2*kt  ][2], sc[mt][2*kt  ][3]);
                pa[mt][2] = packh2(sc[mt][2*kt+1][0], sc[mt][2*kt+1][1]);
                pa[mt][3] = packh2(sc[mt][2*kt+1][2], sc[mt][2*kt+1][3]);
            }
            #pragma unroll
            for (int nt = 0; nt < 8; nt++) {
                const __half* vp = vss + (nt * 8 + r) * VSTRIDE + kt * 16 + 2 * qq;
                uint32_t b0 = *(const uint32_t*)vp;
                uint32_t b1 = *(const uint32_t*)(vp + 8);
                mma_f16(o[0][nt], pa[0], b0, b1);
                mma_f16(o[1][nt], pa[1], b0, b1);
            }
        }
        __syncthreads();
    }

    // ---- finalize ----
    #pragma unroll
    for (int mt = 0; mt < 2; mt++) {
        float l0 = lrow[mt][0];
        l0 += __shfl_xor_sync(0xffffffffu, l0, 1);
        l0 += __shfl_xor_sync(0xffffffffu, l0, 2);
        float l1 = lrow[mt][1];
        l1 += __shfl_xor_sync(0xffffffffu, l1, 1);
        l1 += __shfl_xor_sync(0xffffffffu, l1, 2);
        float inv0 = 1.f / l0, inv1 = 1.f / l1;
        int row0 = q0 + mt * 16 + r;
        float* zp0 = z + (size_t)(b * N_ + row0) * HD + h * D_;
        float* zp1 = zp0 + 8 * (size_t)HD;
        #pragma unroll
        for (int nt = 0; nt < 8; nt++) {
            int col = nt * 8 + 2 * qq;
            float2 v0 = {o[mt][nt][0] * inv0, o[mt][nt][1] * inv0};
            float2 v1 = {o[mt][nt][2] * inv1, o[mt][nt][3] * inv1};
            *(float2*)(zp0 + col) = v0;
            *(float2*)(zp1 + col) = v1;
        }
    }
}

// ---------------------------------------------------------------------------
// Output projection: [16384,512] @ [512,64] + bias (scalar tiled SGEMM)
// ---------------------------------------------------------------------------
__global__ __launch_bounds__(256)
void out_gemm_kernel(const float* __restrict__ A,
                     const float* __restrict__ Bm,
                     const float* __restrict__ bias,
                     float* __restrict__ C)
{
    const int BM = 64, BN = 64, BK = 32;
    __shared__ float As[32][64 + 4];
    __shared__ float Bs[32][64];

    const int tid = threadIdx.x;
    const int tx  = tid % 16;
    const int ty  = tid / 16;
    const int m0  = blockIdx.y * BM;
    const int K = HD, Nn = D_;

    float acc[4][4] = {};

    for (int k0 = 0; k0 < K; k0 += BK) {
        #pragma unroll
        for (int idx = tid; idx < BM * BK / 4; idx += 256) {
            int row = idx / 8;
            int c4  = idx % 8;
            float4 a = *(const float4*)(A + (size_t)(m0 + row) * K + k0 + c4 * 4);
            As[c4 * 4 + 0][row] = a.x;
            As[c4 * 4 + 1][row] = a.y;
            As[c4 * 4 + 2][row] = a.z;
            As[c4 * 4 + 3][row] = a.w;
        }
        #pragma unroll
        for (int idx = tid; idx < BK * BN / 4; idx += 256) {
            int row = idx / 16;
            int c4  = idx % 16;
            *(float4*)&Bs[row][c4 * 4] =
                *(const float4*)(Bm + (size_t)(k0 + row) * Nn + c4 * 4);
        }
        __syncthreads();

        #pragma unroll
        for (int k = 0; k < BK; k++) {
            float4 a = *(const float4*)&As[k][ty * 4];
            float4 b = *(const float4*)&Bs[k][tx * 4];
            float av[4] = {a.x, a.y, a.z, a.w};
            float bv[4] = {b.x, b.y, b.z, b.w};
            #pragma unroll
            for (int i = 0; i < 4; i++)
                #pragma unroll
                for (int j = 0; j < 4; j++)
                    acc[i][j] = fmaf(av[i], bv[j], acc[i][j]);
        }
        __syncthreads();
    }

    #pragma unroll
    for (int i = 0; i < 4; i++) {
        float4 ov;
        ov.x = acc[i][0] + bias[tx * 4 + 0];
        ov.y = acc[i][1] + bias[tx * 4 + 1];
        ov.z = acc[i][2] + bias[tx * 4 + 2];
        ov.w = acc[i][3] + bias[tx * 4 + 3];
        *(float4*)(C + (size_t)(m0 + ty * 4 + i) * Nn + tx * 4) = ov;
    }
}

// ---------------------------------------------------------------------------
extern "C" void kernel_launch(void* const* d_in, const int* in_sizes, int n_in,
                              void* d_out, int out_size)
{
    const float* x    = (const float*)d_in[0];
    const float* Wqkv = (const float*)d_in[1];
    const float* Wout = (const float*)d_in[2];
    const float* bout = (const float*)d_in[3];
    float* out = (float*)d_out;

    float*  qkvp = nullptr;
    __half* vtp  = nullptr;
    float*  zp   = nullptr;
    cudaGetSymbolAddress((void**)&qkvp, g_qkv);
    cudaGetSymbolAddress((void**)&vtp,  g_vt);
    cudaGetSymbolAddress((void**)&zp,   g_z);

    // 1) QKV projection with fused scale / tf32-round / V-transpose epilogue
    {
        dim3 grid(QKVN / 64, M_ / 64);
        qkv_gemm_kernel<<<grid, 256>>>(x, Wqkv, qkvp, vtp);
    }
    // 2) Attention
    {
        const int smem = 2 * 4096 * 4 + 2 * 64 * VSTRIDE * 2;   // 55296 B
        cudaFuncSetAttribute(attn_kernel,
                             cudaFuncAttributeMaxDynamicSharedMemorySize, smem);
        dim3 grid(N_ / 128, B_ * H_);
        attn_kernel<<<grid, 128, smem>>>(qkvp, vtp, zp);
    }
    // 3) Output projection
    {
        dim3 grid(1, M_ / 64);
        out_gemm_kernel<<<grid, 256>>>(zp, Wout, bout, out);
    }
}

// round 4
// speedup vs baseline: 10.2035x; 1.5766x over previous
#include <cuda_runtime.h>
#include <cuda_fp16.h>
#include <stdint.h>

#define B_   8
#define N_   2048
#define D_   64
#define H_   8
#define M_   (B_*N_)        // 16384
#define QKVN 1536
#define HD   512
#define QSCALE (0.125f * 1.44269504088896f)   // 1/sqrt(d) * log2(e)

// Scratch (__device__ globals; allocation-free rule)
__device__ __half g_q [(size_t)M_ * HD];          // [b,tok][h*64+d], pre-scaled
__device__ __half g_k [(size_t)M_ * HD];          // [b,tok][h*64+d]
__device__ __half g_vt[(size_t)B_*H_*D_*N_];      // [bh][d][tok]
__device__ __half g_z [(size_t)M_ * HD];          // [tok][h*64+d]

// ---------------------------------------------------------------------------
// helpers
// ---------------------------------------------------------------------------
__device__ __forceinline__ float ex2f(float x) {
    float y; asm("ex2.approx.f32 %0, %1;" : "=f"(y) : "f"(x)); return y;
}
__device__ __forceinline__ uint32_t packh2(float lo, float hi) {
    uint32_t u;
    asm("cvt.rn.f16x2.f32 %0, %1, %2;" : "=r"(u) : "f"(hi), "f"(lo));
    return u;
}
__device__ __forceinline__ void mma_f16(float d[4], const uint32_t a[4],
                                        uint32_t b0, uint32_t b1) {
    asm volatile(
        "mma.sync.aligned.m16n8k16.row.col.f32.f16.f16.f32 "
        "{%0,%1,%2,%3}, {%4,%5,%6,%7}, {%8,%9}, {%0,%1,%2,%3};\n"
        : "+f"(d[0]), "+f"(d[1]), "+f"(d[2]), "+f"(d[3])
        : "r"(a[0]), "r"(a[1]), "r"(a[2]), "r"(a[3]), "r"(b0), "r"(b1));
}
__device__ __forceinline__ void cp16(uint32_t dst_smem, const void* src) {
    asm volatile("cp.async.cg.shared.global [%0], [%1], 16;\n"
                 :: "r"(dst_smem), "l"(src));
}

// ---------------------------------------------------------------------------
// QKV GEMM (fp16 mma): [16384,64] @ [64,1536]
// Block 128x128, 8 warps (4 M x 2 N), warp tile 32x64.
// Epilogue: Q (*QSCALE) -> g_q fp16; K -> g_k fp16; V -> g_vt fp16 transposed.
// ---------------------------------------------------------------------------
__global__ __launch_bounds__(256)
void qkv_gemm_kernel(const float* __restrict__ x,
                     const float* __restrict__ W,
                     __half* __restrict__ q,
                     __half* __restrict__ kk,
                     __half* __restrict__ vt)
{
    __shared__ __half Wt[128][72];   // [n][k], stride 72 halves (bank 4r+qq)

    const int tid  = threadIdx.x;
    const int warp = tid >> 5, lane = tid & 31;
    const int r = lane >> 2, qq = lane & 3;
    const int wm = warp >> 1, wn = warp & 1;
    const int n0 = blockIdx.x * 128;
    const int m0 = blockIdx.y * 128;

    // W slice [64][128] fp32 -> Wt[n][k] fp16 (transposed)
    for (int idx = tid; idx < 64 * 32; idx += 256) {
        int kw = idx >> 5;          // 0..63
        int c4 = idx & 31;          // n quad
        float4 w = *(const float4*)(W + (size_t)kw * QKVN + n0 + c4 * 4);
        Wt[c4 * 4 + 0][kw] = __float2half_rn(w.x);
        Wt[c4 * 4 + 1][kw] = __float2half_rn(w.y);
        Wt[c4 * 4 + 2][kw] = __float2half_rn(w.z);
        Wt[c4 * 4 + 3][kw] = __float2half_rn(w.w);
    }

    // A-frags straight from gmem (fp32 -> packed fp16)
    uint32_t qa[2][4][4];
    #pragma unroll
    for (int mt = 0; mt < 2; mt++) {
        const float* p0 = x + (size_t)(m0 + wm * 32 + mt * 16 + r) * 64;
        const float* p1 = p0 + 8 * 64;
        #pragma unroll
        for (int kt = 0; kt < 4; kt++) {
            int c = kt * 16 + 2 * qq;
            qa[mt][kt][0] = packh2(p0[c],     p0[c + 1]);
            qa[mt][kt][1] = packh2(p1[c],     p1[c + 1]);
            qa[mt][kt][2] = packh2(p0[c + 8], p0[c + 9]);
            qa[mt][kt][3] = packh2(p1[c + 8], p1[c + 9]);
        }
    }
    __syncthreads();

    float acc[2][8][4] = {};
    #pragma unroll
    for (int kt = 0; kt < 4; kt++) {
        #pragma unroll
        for (int nt = 0; nt < 8; nt++) {
            int n = wn * 64 + nt * 8 + r;
            uint32_t b0 = *(const uint32_t*)&Wt[n][kt * 16 + 2 * qq];
            uint32_t b1 = *(const uint32_t*)&Wt[n][kt * 16 + 2 * qq + 8];
            mma_f16(acc[0][nt], qa[0][kt], b0, b1);
            mma_f16(acc[1][nt], qa[1][kt], b0, b1);
        }
    }

    const int gn = n0 + wn * 64;   // uniform per warp; region uniform per block
    #pragma unroll
    for (int mt = 0; mt < 2; mt++) {
        #pragma unroll
        for (int nt = 0; nt < 8; nt++) {
            int row0 = m0 + wm * 32 + mt * 16 + r;
            int col  = gn + nt * 8 + 2 * qq;
            if (gn < 512) {
                uint32_t v0 = packh2(acc[mt][nt][0] * QSCALE, acc[mt][nt][1] * QSCALE);
                uint32_t v1 = packh2(acc[mt][nt][2] * QSCALE, acc[mt][nt][3] * QSCALE);
                *(uint32_t*)(q + (size_t)row0 * HD + col)       = v0;
                *(uint32_t*)(q + (size_t)(row0 + 8) * HD + col) = v1;
            } else if (gn < 1024) {
                uint32_t v0 = packh2(acc[mt][nt][0], acc[mt][nt][1]);
                uint32_t v1 = packh2(acc[mt][nt][2], acc[mt][nt][3]);
                *(uint32_t*)(kk + (size_t)row0 * HD + col - 512)       = v0;
                *(uint32_t*)(kk + (size_t)(row0 + 8) * HD + col - 512) = v1;
            } else {
                int v  = col - 1024;
                int h  = v >> 6, d = v & 63;
                int b  = row0 >> 11, tok = row0 & 2047;
                size_t base = ((size_t)(b * 8 + h) * 64 + d) * N_;
                vt[base + tok]              = __float2half_rn(acc[mt][nt][0]);
                vt[base + N_ + tok]         = __float2half_rn(acc[mt][nt][1]);
                vt[base + tok + 8]          = __float2half_rn(acc[mt][nt][2]);
                vt[base + N_ + tok + 8]     = __float2half_rn(acc[mt][nt][3]);
            }
        }
    }
}

// ---------------------------------------------------------------------------
// Flash attention: fp16 QK^T + fp16 P@V, exp2 softmax, double-buffered cp.async
// Block: 128 q rows, 4 warps (32 rows each). KV tile = 64.
// ---------------------------------------------------------------------------
#define VSTRIDE 88

__global__ __launch_bounds__(128)
void attn_kernel(const __half* __restrict__ q,
                 const __half* __restrict__ kglb,
                 const __half* __restrict__ vt,
                 __half* __restrict__ z)
{
    __shared__ uint32_t ks[2][64 * 32];          // 64 rows x 128B, chunk-XOR swz
    __shared__ __half   vs[2][64 * VSTRIDE];     // [d][tok], stride 88

    const int tid  = threadIdx.x;
    const int warp = tid >> 5, lane = tid & 31;
    const int r = lane >> 2, qq = lane & 3;
    const int bh = blockIdx.y;
    const int b = bh >> 3, h = bh & 7;
    const int q0 = blockIdx.x * 128 + warp * 32;

    // Q A-frags (fp16, pre-scaled in gmem)
    uint32_t qa[2][4][4];
    #pragma unroll
    for (int mt = 0; mt < 2; mt++) {
        const __half* p0 = q + (size_t)(b * N_ + q0 + mt * 16 + r) * HD + h * D_;
        const __half* p1 = p0 + 8 * (size_t)HD;
        #pragma unroll
        for (int kt = 0; kt < 4; kt++) {
            int c = kt * 16 + 2 * qq;
            qa[mt][kt][0] = *(const uint32_t*)(p0 + c);
            qa[mt][kt][1] = *(const uint32_t*)(p1 + c);
            qa[mt][kt][2] = *(const uint32_t*)(p0 + c + 8);
            qa[mt][kt][3] = *(const uint32_t*)(p1 + c + 8);
        }
    }

    float o[2][8][4] = {};
    float mrow[2][2] = {{-1e30f, -1e30f}, {-1e30f, -1e30f}};
    float lrow[2][2] = {{0.f, 0.f}, {0.f, 0.f}};

    const __half* kb = kglb + (size_t)(b * N_) * HD + h * D_;
    const __half* vb = vt + (size_t)bh * D_ * N_;

    const uint32_t ks_base = (uint32_t)__cvta_generic_to_shared(ks);
    const uint32_t vs_base = (uint32_t)__cvta_generic_to_shared(vs);

#define CP_TILE(stage, j0) do {                                               \
    _Pragma("unroll")                                                         \
    for (int it = 0; it < 4; it++) {                                          \
        int idx = tid + it * 128;                                             \
        int rr = idx >> 3, c4 = idx & 7;                                      \
        cp16(ks_base + (uint32_t)((stage) * 8192 + rr * 128 +                 \
                                  ((c4 ^ (rr & 7)) * 16)),                    \
             kb + (size_t)((j0) + rr) * HD + c4 * 8);                         \
    }                                                                         \
    _Pragma("unroll")                                                         \
    for (int it = 0; it < 4; it++) {                                          \
        int idx = tid + it * 128;                                             \
        int dd = idx >> 3, c8 = idx & 7;                                      \
        cp16(vs_base + (uint32_t)(((stage) * 64 * VSTRIDE + dd * VSTRIDE +    \
                                   c8 * 8) * 2),                              \
             vb + (size_t)dd * N_ + (j0) + c8 * 8);                           \
    }                                                                         \
    asm volatile("cp.async.commit_group;\n" ::);                              \
} while (0)

    CP_TILE(0, 0);

    for (int t = 0; t < N_ / 64; t++) {
        const int s = t & 1;
        if (t < N_ / 64 - 1) {
            CP_TILE(s ^ 1, (t + 1) * 64);
            asm volatile("cp.async.wait_group 1;\n" ::);
        } else {
            asm volatile("cp.async.wait_group 0;\n" ::);
        }
        __syncthreads();

        const uint32_t* kss = ks[s];
        const __half*   vss = vs[s];

        // ---- S = Q @ K^T (fp16 mma, k16 x 4) ----
        float sc[2][8][4] = {};
        #pragma unroll
        for (int kt = 0; kt < 4; kt++) {
            #pragma unroll
            for (int nt = 0; nt < 8; nt++) {
                const uint32_t* kr = kss + (nt * 8 + r) * 32;
                uint32_t b0 = kr[(((2 * kt)     ^ r) << 2) + qq];
                uint32_t b1 = kr[(((2 * kt + 1) ^ r) << 2) + qq];
                mma_f16(sc[0][nt], qa[0][kt], b0, b1);
                mma_f16(sc[1][nt], qa[1][kt], b0, b1);
            }
        }

        // ---- online softmax (log2 domain) ----
        #pragma unroll
        for (int mt = 0; mt < 2; mt++) {
            float mx0 = -1e30f, mx1 = -1e30f;
            #pragma unroll
            for (int nt = 0; nt < 8; nt++) {
                mx0 = fmaxf(mx0, fmaxf(sc[mt][nt][0], sc[mt][nt][1]));
                mx1 = fmaxf(mx1, fmaxf(sc[mt][nt][2], sc[mt][nt][3]));
            }
            mx0 = fmaxf(mx0, __shfl_xor_sync(0xffffffffu, mx0, 1));
            mx0 = fmaxf(mx0, __shfl_xor_sync(0xffffffffu, mx0, 2));
            mx1 = fmaxf(mx1, __shfl_xor_sync(0xffffffffu, mx1, 1));
            mx1 = fmaxf(mx1, __shfl_xor_sync(0xffffffffu, mx1, 2));
            float mn0 = fmaxf(mrow[mt][0], mx0);
            float mn1 = fmaxf(mrow[mt][1], mx1);
            float c0 = ex2f(mrow[mt][0] - mn0);
            float c1 = ex2f(mrow[mt][1] - mn1);
            mrow[mt][0] = mn0; mrow[mt][1] = mn1;
            lrow[mt][0] *= c0; lrow[mt][1] *= c1;
            float l0 = 0.f, l1 = 0.f;
            #pragma unroll
            for (int nt = 0; nt < 8; nt++) {
                o[mt][nt][0] *= c0; o[mt][nt][1] *= c0;
                o[mt][nt][2] *= c1; o[mt][nt][3] *= c1;
                float p0 = ex2f(sc[mt][nt][0] - mn0);
                float p1 = ex2f(sc[mt][nt][1] - mn0);
                float p2 = ex2f(sc[mt][nt][2] - mn1);
                float p3 = ex2f(sc[mt][nt][3] - mn1);
                l0 += p0 + p1; l1 += p2 + p3;
                sc[mt][nt][0] = p0; sc[mt][nt][1] = p1;
                sc[mt][nt][2] = p2; sc[mt][nt][3] = p3;
            }
            lrow[mt][0] += l0; lrow[mt][1] += l1;
        }

        // ---- O += P @ V (fp16; P C-frag == A-frag) ----
        #pragma unroll
        for (int kt = 0; kt < 4; kt++) {
            uint32_t pa[2][4];
            #pragma unroll
            for (int mt = 0; mt < 2; mt++) {
                pa[mt][0] = packh2(sc[mt][2*kt  ][0], sc[mt][2*kt  ][1]);
                pa[mt][1] = packh2(sc[mt][2*kt  ][2], sc[mt][2*kt  ][3]);
                pa[mt][2] = packh2(sc[mt][2*kt+1][0], sc[mt][2*kt+1][1]);
                pa[mt][3] = packh2(sc[mt][2*kt+1][2], sc[mt][2*kt+1][3]);
            }
            #pragma unroll
            for (int nt = 0; nt < 8; nt++) {
                const __half* vp = vss + (nt * 8 + r) * VSTRIDE + kt * 16 + 2 * qq;
                uint32_t b0 = *(const uint32_t*)vp;
                uint32_t b1 = *(const uint32_t*)(vp + 8);
                mma_f16(o[0][nt], pa[0], b0, b1);
                mma_f16(o[1][nt], pa[1], b0, b1);
            }
        }
        __syncthreads();
    }

    // ---- finalize: z fp16 ----
    #pragma unroll
    for (int mt = 0; mt < 2; mt++) {
        float l0 = lrow[mt][0];
        l0 += __shfl_xor_sync(0xffffffffu, l0, 1);
        l0 += __shfl_xor_sync(0xffffffffu, l0, 2);
        float l1 = lrow[mt][1];
        l1 += __shfl_xor_sync(0xffffffffu, l1, 1);
        l1 += __shfl_xor_sync(0xffffffffu, l1, 2);
        float inv0 = 1.f / l0, inv1 = 1.f / l1;
        int row0 = q0 + mt * 16 + r;
        __half* zp0 = z + (size_t)(b * N_ + row0) * HD + h * D_;
        __half* zp1 = zp0 + 8 * (size_t)HD;
        #pragma unroll
        for (int nt = 0; nt < 8; nt++) {
            int col = nt * 8 + 2 * qq;
            *(uint32_t*)(zp0 + col) = packh2(o[mt][nt][0] * inv0, o[mt][nt][1] * inv0);
            *(uint32_t*)(zp1 + col) = packh2(o[mt][nt][2] * inv1, o[mt][nt][3] * inv1);
        }
    }
}

// ---------------------------------------------------------------------------
// Output projection (fp16 mma): [16384,512] @ [512,64] + bias -> fp32
// Block: 64 rows, 4 warps (16 rows each), all 64 cols; K pipelined in 64-chunks
// ---------------------------------------------------------------------------
__global__ __launch_bounds__(128)
void out_gemm_kernel(const __half* __restrict__ z,
                     const float* __restrict__ W,
                     const float* __restrict__ bias,
                     float* __restrict__ out)
{
    extern __shared__ char smem_raw[];
    __half*   wt  = (__half*)smem_raw;                 // [64][520] halves
    uint32_t* as  = (uint32_t*)(smem_raw + 64 * 520 * 2); // 2 x 64 rows x 32 w

    const int tid  = threadIdx.x;
    const int warp = tid >> 5, lane = tid & 31;
    const int r = lane >> 2, qq = lane & 3;
    const int m0 = blockIdx.x * 64;

    // Wout [512][64] fp32 -> wt[n][k] fp16 transposed (stride 520)
    for (int idx = tid; idx < 512 * 16; idx += 128) {
        int kw = idx >> 4, c4 = idx & 15;
        float4 w = *(const float4*)(W + (size_t)kw * 64 + c4 * 4);
        wt[(c4 * 4 + 0) * 520 + kw] = __float2half_rn(w.x);
        wt[(c4 * 4 + 1) * 520 + kw] = __float2half_rn(w.y);
        wt[(c4 * 4 + 2) * 520 + kw] = __float2half_rn(w.z);
        wt[(c4 * 4 + 3) * 520 + kw] = __float2half_rn(w.w);
    }

    const uint32_t as_base = (uint32_t)__cvta_generic_to_shared(as);

#define CPA(stage, kc) do {                                                   \
    _Pragma("unroll")                                                         \
    for (int it = 0; it < 4; it++) {                                          \
        int idx = tid + it * 128;                                             \
        int rr = idx >> 3, c4 = idx & 7;                                      \
        cp16(as_base + (uint32_t)((stage) * 8192 + rr * 128 +                 \
                                  ((c4 ^ (rr & 7)) * 16)),                    \
             z + (size_t)(m0 + rr) * HD + (kc) * 64 + c4 * 8);                \
    }                                                                         \
    asm volatile("cp.async.commit_group;\n" ::);                              \
} while (0)

    CPA(0, 0);

    float acc[8][4] = {};

    for (int kc = 0; kc < 8; kc++) {
        const int s = kc & 1;
        if (kc < 7) {
            CPA(s ^ 1, kc + 1);
            asm volatile("cp.async.wait_group 1;\n" ::);
        } else {
            asm volatile("cp.async.wait_group 0;\n" ::);
        }
        __syncthreads();

        const uint32_t* asw = as + s * 2048;
        const int rowa0 = warp * 16 + r;
        const int rowa1 = rowa0 + 8;

        #pragma unroll
        for (int kt = 0; kt < 4; kt++) {
            uint32_t a[4];
            a[0] = asw[rowa0 * 32 + (((2*kt)   ^ r) << 2) + qq];
            a[1] = asw[rowa1 * 32 + (((2*kt)   ^ r) << 2) + qq];
            a[2] = asw[rowa0 * 32 + (((2*kt+1) ^ r) << 2) + qq];
            a[3] = asw[rowa1 * 32 + (((2*kt+1) ^ r) << 2) + qq];
            #pragma unroll
            for (int nt = 0; nt < 8; nt++) {
                int n = nt * 8 + r;
                const __half* wp = wt + n * 520 + kc * 64 + kt * 16 + 2 * qq;
                uint32_t b0 = *(const uint32_t*)wp;
                uint32_t b1 = *(const uint32_t*)(wp + 8);
                mma_f16(acc[nt], a, b0, b1);
            }
        }
        __syncthreads();
    }

    #pragma unroll
    for (int nt = 0; nt < 8; nt++) {
        int row0 = m0 + warp * 16 + r;
        int col  = nt * 8 + 2 * qq;
        float bx = bias[col], by = bias[col + 1];
        float2 v0 = {acc[nt][0] + bx, acc[nt][1] + by};
        float2 v1 = {acc[nt][2] + bx, acc[nt][3] + by};
        *(float2*)(out + (size_t)row0 * 64 + col)       = v0;
        *(float2*)(out + (size_t)(row0 + 8) * 64 + col) = v1;
    }
}

// ---------------------------------------------------------------------------
extern "C" void kernel_launch(void* const* d_in, const int* in_sizes, int n_in,
                              void* d_out, int out_size)
{
    const float* x    = (const float*)d_in[0];
    const float* Wqkv = (const float*)d_in[1];
    const float* Wout = (const float*)d_in[2];
    const float* bout = (const float*)d_in[3];
    float* out = (float*)d_out;

    __half *qp, *kp, *vtp, *zp;
    cudaGetSymbolAddress((void**)&qp,  g_q);
    cudaGetSymbolAddress((void**)&kp,  g_k);
    cudaGetSymbolAddress((void**)&vtp, g_vt);
    cudaGetSymbolAddress((void**)&zp,  g_z);

    // 1) QKV projection (fp16 mma, fused epilogue)
    {
        dim3 grid(QKVN / 128, M_ / 128);
        qkv_gemm_kernel<<<grid, 256>>>(x, Wqkv, qp, kp, vtp);
    }
    // 2) Attention
    {
        dim3 grid(N_ / 128, B_ * H_);
        attn_kernel<<<grid, 128>>>(qp, kp, vtp, zp);
    }
    // 3) Output projection (fp16 mma)
    {
        const int smem = 64 * 520 * 2 + 2 * 8192;   // 82944 B
        cudaFuncSetAttribute(out_gemm_kernel,
                             cudaFuncAttributeMaxDynamicSharedMemorySize, smem);
        out_gemm_kernel<<<M_ / 64, 128, smem>>>(zp, Wout, bout, out);
    }
}

// round 5
// speedup vs baseline: 10.6549x; 1.0442x over previous
#include <cuda_runtime.h>
#include <cuda_fp16.h>
#include <stdint.h>

#define B_   8
#define N_   2048
#define D_   64
#define H_   8
#define M_   (B_*N_)        // 16384
#define QKVN 1536
#define HD   512
#define QSCALE (0.125f * 1.44269504088896f)   // 1/sqrt(d) * log2(e)

// Scratch (__device__ globals; allocation-free rule)
__device__ __half g_q [(size_t)M_ * HD];
__device__ __half g_k [(size_t)M_ * HD];
__device__ __half g_vt[(size_t)B_*H_*D_*N_];      // [bh][d][tok]
__device__ __half g_z [(size_t)M_ * HD];
__device__ __half g_wt[64 * 520];                 // Wout^T fp16 [n][k], stride 520

// ---------------------------------------------------------------------------
// helpers
// ---------------------------------------------------------------------------
__device__ __forceinline__ float ex2f(float x) {
    float y; asm("ex2.approx.f32 %0, %1;" : "=f"(y) : "f"(x)); return y;
}
__device__ __forceinline__ uint32_t ex2h2(uint32_t x) {
    uint32_t y; asm("ex2.approx.f16x2 %0, %1;" : "=r"(y) : "r"(x)); return y;
}
__device__ __forceinline__ uint32_t packh2(float lo, float hi) {
    uint32_t u;
    asm("cvt.rn.f16x2.f32 %0, %1, %2;" : "=r"(u) : "f"(hi), "f"(lo));
    return u;
}
__device__ __forceinline__ void mma_f16(float d[4], const uint32_t a[4],
                                        uint32_t b0, uint32_t b1) {
    asm volatile(
        "mma.sync.aligned.m16n8k16.row.col.f32.f16.f16.f32 "
        "{%0,%1,%2,%3}, {%4,%5,%6,%7}, {%8,%9}, {%0,%1,%2,%3};\n"
        : "+f"(d[0]), "+f"(d[1]), "+f"(d[2]), "+f"(d[3])
        : "r"(a[0]), "r"(a[1]), "r"(a[2]), "r"(a[3]), "r"(b0), "r"(b1));
}
__device__ __forceinline__ void cp16(uint32_t dst_smem, const void* src) {
    asm volatile("cp.async.cg.shared.global [%0], [%1], 16;\n"
                 :: "r"(dst_smem), "l"(src));
}

// ---------------------------------------------------------------------------
// Wout fp32 [512][64] -> fp16 transposed [n][k] stride 520
// ---------------------------------------------------------------------------
__global__ __launch_bounds__(256)
void wconv_kernel(const float* __restrict__ W, __half* __restrict__ wt)
{
    int idx = blockIdx.x * 256 + threadIdx.x;   // 32768 total
    int k = idx >> 6, n = idx & 63;
    wt[n * 520 + k] = __float2half_rn(W[idx]);
}

// ---------------------------------------------------------------------------
// QKV GEMM (fp16 mma): [16384,64] @ [64,1536]
// Block 128x128, 8 warps. Epilogue: Q (*QSCALE) / K -> fp16; V -> fp16
// transposed via smem staging (coalesced STG.128).
// ---------------------------------------------------------------------------
__global__ __launch_bounds__(256)
void qkv_gemm_kernel(const float* __restrict__ x,
                     const float* __restrict__ W,
                     __half* __restrict__ q,
                     __half* __restrict__ kk,
                     __half* __restrict__ vt)
{
    __shared__ __align__(16) char smem_u[128 * 136 * 2];   // 34816 B union
    __half (*Wt)[72]  = (__half(*)[72])smem_u;             // [n][k]
    __half (*sv)[136] = (__half(*)[136])smem_u;            // [col][tok] (V)

    const int tid  = threadIdx.x;
    const int warp = tid >> 5, lane = tid & 31;
    const int r = lane >> 2, qq = lane & 3;
    const int wm = warp >> 1, wn = warp & 1;
    const int n0 = blockIdx.x * 128;
    const int m0 = blockIdx.y * 128;

    // W slice [64][128] fp32 -> Wt[n][k] fp16 (transposed)
    for (int idx = tid; idx < 64 * 32; idx += 256) {
        int kw = idx >> 5;
        int c4 = idx & 31;
        float4 w = *(const float4*)(W + (size_t)kw * QKVN + n0 + c4 * 4);
        Wt[c4 * 4 + 0][kw] = __float2half_rn(w.x);
        Wt[c4 * 4 + 1][kw] = __float2half_rn(w.y);
        Wt[c4 * 4 + 2][kw] = __float2half_rn(w.z);
        Wt[c4 * 4 + 3][kw] = __float2half_rn(w.w);
    }

    // A-frags straight from gmem (fp32 -> packed fp16)
    uint32_t qa[2][4][4];
    #pragma unroll
    for (int mt = 0; mt < 2; mt++) {
        const float* p0 = x + (size_t)(m0 + wm * 32 + mt * 16 + r) * 64;
        const float* p1 = p0 + 8 * 64;
        #pragma unroll
        for (int kt = 0; kt < 4; kt++) {
            int c = kt * 16 + 2 * qq;
            qa[mt][kt][0] = packh2(p0[c],     p0[c + 1]);
            qa[mt][kt][1] = packh2(p1[c],     p1[c + 1]);
            qa[mt][kt][2] = packh2(p0[c + 8], p0[c + 9]);
            qa[mt][kt][3] = packh2(p1[c + 8], p1[c + 9]);
        }
    }
    __syncthreads();

    float acc[2][8][4] = {};
    #pragma unroll
    for (int kt = 0; kt < 4; kt++) {
        #pragma unroll
        for (int nt = 0; nt < 8; nt++) {
            int n = wn * 64 + nt * 8 + r;
            uint32_t b0 = *(const uint32_t*)&Wt[n][kt * 16 + 2 * qq];
            uint32_t b1 = *(const uint32_t*)&Wt[n][kt * 16 + 2 * qq + 8];
            mma_f16(acc[0][nt], qa[0][kt], b0, b1);
            mma_f16(acc[1][nt], qa[1][kt], b0, b1);
        }
    }

    if (n0 < 1024) {
        // ---- Q / K: direct stores ----
        const float s = (n0 < 512) ? QSCALE : 1.0f;
        __half* dst = (n0 < 512) ? q : kk;
        const int cbase = (n0 < 512) ? n0 : (n0 - 512);
        #pragma unroll
        for (int mt = 0; mt < 2; mt++) {
            #pragma unroll
            for (int nt = 0; nt < 8; nt++) {
                int row0 = m0 + wm * 32 + mt * 16 + r;
                int col  = cbase + wn * 64 + nt * 8 + 2 * qq;
                uint32_t v0 = packh2(acc[mt][nt][0] * s, acc[mt][nt][1] * s);
                uint32_t v1 = packh2(acc[mt][nt][2] * s, acc[mt][nt][3] * s);
                *(uint32_t*)(dst + (size_t)row0 * HD + col)       = v0;
                *(uint32_t*)(dst + (size_t)(row0 + 8) * HD + col) = v1;
            }
        }
    } else {
        // ---- V: transpose via smem, then coalesced STG.128 ----
        __syncthreads();                       // Wt reads done
        #pragma unroll
        for (int mt = 0; mt < 2; mt++) {
            #pragma unroll
            for (int nt = 0; nt < 8; nt++) {
                int row_l = wm * 32 + mt * 16 + r;
                int col_l = wn * 64 + nt * 8 + 2 * qq;
                sv[col_l    ][row_l]     = __float2half_rn(acc[mt][nt][0]);
                sv[col_l + 1][row_l]     = __float2half_rn(acc[mt][nt][1]);
                sv[col_l    ][row_l + 8] = __float2half_rn(acc[mt][nt][2]);
                sv[col_l + 1][row_l + 8] = __float2half_rn(acc[mt][nt][3]);
            }
        }
        __syncthreads();
        const int h0   = (n0 - 1024) >> 6;
        const int b    = m0 >> 11;
        const int tok0 = m0 & 2047;
        for (int idx = tid; idx < 128 * 16; idx += 256) {
            int col = idx >> 4, c8 = idx & 15;
            uint4 v = *(uint4*)&sv[col][c8 * 8];
            int h = h0 + (col >> 6), d = col & 63;
            *(uint4*)(vt + ((size_t)((b * 8 + h) * 64 + d)) * N_ +
                      tok0 + c8 * 8) = v;
        }
    }
}

// ---------------------------------------------------------------------------
// Flash attention: fp16 QK^T + fp16 P@V, f16x2 exp2, l via ones-column MMA,
// predicated rescale, double-buffered cp.async.
// ---------------------------------------------------------------------------
#define VSTRIDE 88

__global__ __launch_bounds__(128)
void attn_kernel(const __half* __restrict__ q,
                 const __half* __restrict__ kglb,
                 const __half* __restrict__ vt,
                 __half* __restrict__ z)
{
    __shared__ uint32_t ks[2][64 * 32];
    __shared__ __half   vs[2][64 * VSTRIDE];

    const int tid  = threadIdx.x;
    const int warp = tid >> 5, lane = tid & 31;
    const int r = lane >> 2, qq = lane & 3;
    const int bh = blockIdx.y;
    const int b = bh >> 3, h = bh & 7;
    const int q0 = blockIdx.x * 128 + warp * 32;
    const uint32_t ONE2 = 0x3C003C00u;

    uint32_t qa[2][4][4];
    #pragma unroll
    for (int mt = 0; mt < 2; mt++) {
        const __half* p0 = q + (size_t)(b * N_ + q0 + mt * 16 + r) * HD + h * D_;
        const __half* p1 = p0 + 8 * (size_t)HD;
        #pragma unroll
        for (int kt = 0; kt < 4; kt++) {
            int c = kt * 16 + 2 * qq;
            qa[mt][kt][0] = *(const uint32_t*)(p0 + c);
            qa[mt][kt][1] = *(const uint32_t*)(p1 + c);
            qa[mt][kt][2] = *(const uint32_t*)(p0 + c + 8);
            qa[mt][kt][3] = *(const uint32_t*)(p1 + c + 8);
        }
    }

    float o[2][8][4] = {};
    float lf[2][4] = {};
    float mrow[2][2] = {{-1e30f, -1e30f}, {-1e30f, -1e30f}};

    const __half* kb = kglb + (size_t)(b * N_) * HD + h * D_;
    const __half* vb = vt + (size_t)bh * D_ * N_;

    const uint32_t ks_base = (uint32_t)__cvta_generic_to_shared(ks);
    const uint32_t vs_base = (uint32_t)__cvta_generic_to_shared(vs);

#define CP_TILE(stage, j0) do {                                               \
    _Pragma("unroll")                                                         \
    for (int it = 0; it < 4; it++) {                                          \
        int idx = tid + it * 128;                                             \
        int rr = idx >> 3, c4 = idx & 7;                                      \
        cp16(ks_base + (uint32_t)((stage) * 8192 + rr * 128 +                 \
                                  ((c4 ^ (rr & 7)) * 16)),                    \
             kb + (size_t)((j0) + rr) * HD + c4 * 8);                         \
    }                                                                         \
    _Pragma("unroll")                                                         \
    for (int it = 0; it < 4; it++) {                                          \
        int idx = tid + it * 128;                                             \
        int dd = idx >> 3, c8 = idx & 7;                                      \
        cp16(vs_base + (uint32_t)(((stage) * 64 * VSTRIDE + dd * VSTRIDE +    \
                                   c8 * 8) * 2),                              \
             vb + (size_t)dd * N_ + (j0) + c8 * 8);                           \
    }                                                                         \
    asm volatile("cp.async.commit_group;\n" ::);                              \
} while (0)

    CP_TILE(0, 0);

    for (int t = 0; t < N_ / 64; t++) {
        const int s = t & 1;
        if (t < N_ / 64 - 1) {
            CP_TILE(s ^ 1, (t + 1) * 64);
            asm volatile("cp.async.wait_group 1;\n" ::);
        } else {
            asm volatile("cp.async.wait_group 0;\n" ::);
        }
        __syncthreads();

        const uint32_t* kss = ks[s];
        const __half*   vss = vs[s];

        // ---- S = Q @ K^T (fp16 mma) ----
        float sc[2][8][4] = {};
        #pragma unroll
        for (int kt = 0; kt < 4; kt++) {
            #pragma unroll
            for (int nt = 0; nt < 8; nt++) {
                const uint32_t* kr = kss + (nt * 8 + r) * 32;
                uint32_t b0 = kr[(((2 * kt)     ^ r) << 2) + qq];
                uint32_t b1 = kr[(((2 * kt + 1) ^ r) << 2) + qq];
                mma_f16(sc[0][nt], qa[0][kt], b0, b1);
                mma_f16(sc[1][nt], qa[1][kt], b0, b1);
            }
        }

        // ---- softmax: max -> (predicated rescale) -> P in f16x2 ----
        uint32_t pl[2][8], ph[2][8];
        #pragma unroll
        for (int mt = 0; mt < 2; mt++) {
            float mx0 = -1e30f, mx1 = -1e30f;
            #pragma unroll
            for (int nt = 0; nt < 8; nt++) {
                mx0 = fmaxf(mx0, fmaxf(sc[mt][nt][0], sc[mt][nt][1]));
                mx1 = fmaxf(mx1, fmaxf(sc[mt][nt][2], sc[mt][nt][3]));
            }
            mx0 = fmaxf(mx0, __shfl_xor_sync(0xffffffffu, mx0, 1));
            mx0 = fmaxf(mx0, __shfl_xor_sync(0xffffffffu, mx0, 2));
            mx1 = fmaxf(mx1, __shfl_xor_sync(0xffffffffu, mx1, 1));
            mx1 = fmaxf(mx1, __shfl_xor_sync(0xffffffffu, mx1, 2));
            float mn0 = fmaxf(mrow[mt][0], mx0);
            float mn1 = fmaxf(mrow[mt][1], mx1);

            if (__any_sync(0xffffffffu,
                           (mn0 > mrow[mt][0]) || (mn1 > mrow[mt][1]))) {
                float c0 = ex2f(mrow[mt][0] - mn0);
                float c1 = ex2f(mrow[mt][1] - mn1);
                #pragma unroll
                for (int nt = 0; nt < 8; nt++) {
                    o[mt][nt][0] *= c0; o[mt][nt][1] *= c0;
                    o[mt][nt][2] *= c1; o[mt][nt][3] *= c1;
                }
                lf[mt][0] *= c0; lf[mt][1] *= c0;
                lf[mt][2] *= c1; lf[mt][3] *= c1;
                mrow[mt][0] = mn0; mrow[mt][1] = mn1;
            }
            #pragma unroll
            for (int nt = 0; nt < 8; nt++) {
                pl[mt][nt] = ex2h2(packh2(sc[mt][nt][0] - mn0,
                                          sc[mt][nt][1] - mn0));
                ph[mt][nt] = ex2h2(packh2(sc[mt][nt][2] - mn1,
                                          sc[mt][nt][3] - mn1));
            }
        }

        // ---- O += P @ V ; l += P @ ones (extra n8 column) ----
        #pragma unroll
        for (int kt = 0; kt < 4; kt++) {
            uint32_t pa[2][4];
            #pragma unroll
            for (int mt = 0; mt < 2; mt++) {
                pa[mt][0] = pl[mt][2 * kt];
                pa[mt][1] = ph[mt][2 * kt];
                pa[mt][2] = pl[mt][2 * kt + 1];
                pa[mt][3] = ph[mt][2 * kt + 1];
            }
            #pragma unroll
            for (int nt = 0; nt < 8; nt++) {
                const __half* vp = vss + (nt * 8 + r) * VSTRIDE + kt * 16 + 2 * qq;
                uint32_t b0 = *(const uint32_t*)vp;
                uint32_t b1 = *(const uint32_t*)(vp + 8);
                mma_f16(o[0][nt], pa[0], b0, b1);
                mma_f16(o[1][nt], pa[1], b0, b1);
            }
            mma_f16(lf[0], pa[0], ONE2, ONE2);
            mma_f16(lf[1], pa[1], ONE2, ONE2);
        }
        __syncthreads();
    }

    // ---- finalize (lf already holds full row sums; no shuffles) ----
    #pragma unroll
    for (int mt = 0; mt < 2; mt++) {
        float inv0 = 1.f / lf[mt][0];
        float inv1 = 1.f / lf[mt][2];
        int row0 = q0 + mt * 16 + r;
        __half* zp0 = z + (size_t)(b * N_ + row0) * HD + h * D_;
        __half* zp1 = zp0 + 8 * (size_t)HD;
        #pragma unroll
        for (int nt = 0; nt < 8; nt++) {
            int col = nt * 8 + 2 * qq;
            *(uint32_t*)(zp0 + col) = packh2(o[mt][nt][0] * inv0,
                                             o[mt][nt][1] * inv0);
            *(uint32_t*)(zp1 + col) = packh2(o[mt][nt][2] * inv1,
                                             o[mt][nt][3] * inv1);
        }
    }
}

// ---------------------------------------------------------------------------
// Output projection (fp16 mma): [16384,512] @ [512,64] + bias -> fp32
// 256 threads, 128 rows/block; W pre-converted fp16, cp.async everywhere.
// ---------------------------------------------------------------------------
__global__ __launch_bounds__(256)
void out_gemm_kernel(const __half* __restrict__ z,
                     const __half* __restrict__ wt,
                     const float* __restrict__ bias,
                     float* __restrict__ out)
{
    extern __shared__ char smem_raw[];
    __half*   swt = (__half*)smem_raw;                       // [64][520]
    uint32_t* as  = (uint32_t*)(smem_raw + 64 * 520 * 2);    // 2 x 128 x 32 w

    const int tid  = threadIdx.x;
    const int warp = tid >> 5, lane = tid & 31;
    const int r = lane >> 2, qq = lane & 3;
    const int m0 = blockIdx.x * 128;

    const uint32_t wt_base = (uint32_t)__cvta_generic_to_shared(swt);
    const uint32_t as_base = (uint32_t)__cvta_generic_to_shared(as);

#define CPA(stage, kc) do {                                                   \
    _Pragma("unroll")                                                         \
    for (int it = 0; it < 4; it++) {                                          \
        int idx = tid + it * 256;                                             \
        int rr = idx >> 3, c4 = idx & 7;                                      \
        cp16(as_base + (uint32_t)((stage) * 16384 + rr * 128 +                \
                                  ((c4 ^ (rr & 7)) * 16)),                    \
             z + (size_t)(m0 + rr) * HD + (kc) * 64 + c4 * 8);                \
    }                                                                         \
    asm volatile("cp.async.commit_group;\n" ::);                              \
} while (0)

    // group0: full W tile + A stage 0
    #pragma unroll
    for (int it = 0; it < 16; it++) {
        int idx = tid + it * 256;               // 4096 chunks
        int n = idx >> 6, c = idx & 63;
        cp16(wt_base + (uint32_t)(n * 1040 + c * 16), wt + n * 520 + c * 8);
    }
    CPA(0, 0);

    float acc[8][4] = {};

    for (int kc = 0; kc < 8; kc++) {
        const int s = kc & 1;
        if (kc < 7) {
            CPA(s ^ 1, kc + 1);
            asm volatile("cp.async.wait_group 1;\n" ::);
        } else {
            asm volatile("cp.async.wait_group 0;\n" ::);
        }
        __syncthreads();

        const uint32_t* asw = as + s * 4096;
        const int rowa0 = warp * 16 + r;
        const int rowa1 = rowa0 + 8;

        #pragma unroll
        for (int kt = 0; kt < 4; kt++) {
            uint32_t a[4];
            a[0] = asw[rowa0 * 32 + (((2*kt)   ^ r) << 2) + qq];
            a[1] = asw[rowa1 * 32 + (((2*kt)   ^ r) << 2) + qq];
            a[2] = asw[rowa0 * 32 + (((2*kt+1) ^ r) << 2) + qq];
            a[3] = asw[rowa1 * 32 + (((2*kt+1) ^ r) << 2) + qq];
            #pragma unroll
            for (int nt = 0; nt < 8; nt++) {
                int n = nt * 8 + r;
                const __half* wp = swt + n * 520 + kc * 64 + kt * 16 + 2 * qq;
                uint32_t b0 = *(const uint32_t*)wp;
                uint32_t b1 = *(const uint32_t*)(wp + 8);
                mma_f16(acc[nt], a, b0, b1);
            }
        }
        __syncthreads();
    }

    #pragma unroll
    for (int nt = 0; nt < 8; nt++) {
        int row0 = m0 + warp * 16 + r;
        int col  = nt * 8 + 2 * qq;
        float bx = bias[col], by = bias[col + 1];
        float2 v0 = {acc[nt][0] + bx, acc[nt][1] + by};
        float2 v1 = {acc[nt][2] + bx, acc[nt][3] + by};
        *(float2*)(out + (size_t)row0 * 64 + col)       = v0;
        *(float2*)(out + (size_t)(row0 + 8) * 64 + col) = v1;
    }
}

// ---------------------------------------------------------------------------
extern "C" void kernel_launch(void* const* d_in, const int* in_sizes, int n_in,
                              void* d_out, int out_size)
{
    const float* x    = (const float*)d_in[0];
    const float* Wqkv = (const float*)d_in[1];
    const float* Wout = (const float*)d_in[2];
    const float* bout = (const float*)d_in[3];
    float* out = (float*)d_out;

    __half *qp, *kp, *vtp, *zp, *wtp;
    cudaGetSymbolAddress((void**)&qp,  g_q);
    cudaGetSymbolAddress((void**)&kp,  g_k);
    cudaGetSymbolAddress((void**)&vtp, g_vt);
    cudaGetSymbolAddress((void**)&zp,  g_z);
    cudaGetSymbolAddress((void**)&wtp, g_wt);

    // 0) Wout -> fp16 transposed (tiny, overlaps nothing critical)
    wconv_kernel<<<128, 256>>>(Wout, wtp);
    // 1) QKV projection
    {
        dim3 grid(QKVN / 128, M_ / 128);
        qkv_gemm_kernel<<<grid, 256>>>(x, Wqkv, qp, kp, vtp);
    }
    // 2) Attention
    {
        dim3 grid(N_ / 128, B_ * H_);
        attn_kernel<<<grid, 128>>>(qp, kp, vtp, zp);
    }
    // 3) Output projection
    {
        const int smem = 64 * 520 * 2 + 2 * 16384;   // 99328 B
        cudaFuncSetAttribute(out_gemm_kernel,
                             cudaFuncAttributeMaxDynamicSharedMemorySize, smem);
        out_gemm_kernel<<<M_ / 128, 256, smem>>>(zp, wtp, bout, out);
    }
}